// round 4
// baseline (speedup 1.0000x reference)
#include <cuda_runtime.h>
#include <math.h>

// ---------------------------------------------------------------------------
// CRF-as-RNN forward, fully fused into ONE persistent kernel.
//  - spatial filter: exact separable 1D passes (pre-normalized G)
//  - bilateral filter: low-rank feature map, degree-5 Taylor, R=252 monomials
//  - grid-wide software barrier (148 blocks == 148 SMs, all resident)
// ---------------------------------------------------------------------------

static constexpr int HW   = 96;
static constexpr int NPIX = HW * HW;      // 9216
static constexpr int NC   = 21;
static constexpr int RD   = 252;          // monomials deg<=5 in 5 vars
static constexpr int RSPLIT = 7;
static constexpr int RCH  = RD / RSPLIT;  // 36
static constexpr int GRID = 148;
static constexpr int TPB  = 256;
static constexpr int NTHR = GRID * TPB;   // 37888

// ------------------------- device scratch ----------------------------------
__device__ float g_u[NC * NPIX];
__device__ float g_s[NC * NPIX];
__device__ float g_tmp[NC * NPIX];
__device__ float g_sp[NC * NPIX];
__device__ float g_Gn[HW * HW];
__device__ float g_GnT[HW * HW];
__device__ float g_gsum[HW];
__device__ float g_phiT[(size_t)RD * NPIX];      // 9.3 MB [r][n]
__device__ float g_M0[RD];
__device__ float g_normbl[NPIX];
__device__ float g_part[RSPLIT * NC * NPIX];     // 5.4 MB
__device__ float g_mom[NC * RD];
__device__ float g_W1[NC * NC], g_W2[NC * NC], g_cvec[NC];
__device__ unsigned g_monoE[RD];
__device__ float g_monoC[RD];
__device__ unsigned g_barCount = 0;
__device__ volatile unsigned g_barGen = 0;

// grid-wide barrier: sense-reversal counter. Safe: 148 blocks, 1 per SM.
__device__ __forceinline__ void gsync() {
    __syncthreads();
    __threadfence();                       // release (drains global stores)
    if (threadIdx.x == 0) {
        unsigned my = g_barGen;
        if (atomicAdd(&g_barCount, 1u) == GRID - 1u) {
            g_barCount = 0u;
            __threadfence();
            g_barGen = my + 1u;
        } else {
            while (g_barGen == my) { __nanosleep(64); }
        }
    }
    __syncthreads();
    __threadfence();                       // acquire (CCTL.IVALL: fresh L1)
}

__global__ __launch_bounds__(TPB, 1) void crf_all(
    const float* __restrict__ img,
    const float* __restrict__ net_w, const float* __restrict__ net_b,
    const float* __restrict__ sp_w,  const float* __restrict__ sp_b,
    const float* __restrict__ bl_w,  const float* __restrict__ bl_b,
    const float* __restrict__ comp_w,const float* __restrict__ comp_b,
    float* __restrict__ out)
{
    __shared__ __align__(16) char sraw[33024];
    const int tid  = threadIdx.x;
    const int bid  = blockIdx.x;
    const int gtid = bid * TPB + tid;
    const int lane = tid & 31;

    // ======================= phase 0: independent setup =====================
    if (gtid == 0) {
        const float rs[6] = {1.0f, 1.0f, 0.70710678f, 0.40824829f,
                             0.20412415f, 0.091287093f};
        int r = 0;
        for (int m0 = 0; m0 <= 5; m0++)
        for (int m1 = 0; m1 <= 5 - m0; m1++)
        for (int m2 = 0; m2 <= 5 - m0 - m1; m2++)
        for (int m3 = 0; m3 <= 5 - m0 - m1 - m2; m3++)
        for (int m4 = 0; m4 <= 5 - m0 - m1 - m2 - m3; m4++) {
            g_monoE[r] = (unsigned)(m0 | (m1 << 3) | (m2 << 6) | (m3 << 9) | (m4 << 12));
            g_monoC[r] = rs[m0] * rs[m1] * rs[m2] * rs[m3] * rs[m4];
            r++;
        }
    }
    for (int t = gtid; t < HW * HW; t += NTHR) {
        int i = t / HW, j = t % HW;
        float d = (float)(i - j) * (1.0f / 3.0f);
        g_Gn[t] = expf(-0.5f * d * d);
    }
    for (int t = gtid; t < HW; t += NTHR) {
        float acc = 0.0f;
        for (int j = 0; j < HW; j++) {
            float d = (float)(t - j) * (1.0f / 3.0f);
            acc += expf(-0.5f * d * d);
        }
        g_gsum[t] = acc;
    }
    for (int t = gtid; t < NC * NC; t += NTHR) {
        int o = t / NC, k = t % NC;
        float a1 = 0.0f, a2 = 0.0f;
        for (int c = 0; c < NC; c++) {
            a1 += comp_w[o * NC + c] * sp_w[c * NC + k];
            a2 += comp_w[o * NC + c] * bl_w[c * NC + k];
        }
        g_W1[t] = a1; g_W2[t] = a2;
    }
    for (int t = gtid; t < NC; t += NTHR) {
        float cv = comp_b[t];
        for (int c = 0; c < NC; c++) cv += comp_w[t * NC + c] * (sp_b[c] + bl_b[c]);
        g_cvec[t] = cv;
    }
    for (int t = gtid; t < NC * RD; t += NTHR) g_mom[t] = 0.0f;
    // unary 3x3 SAME conv
    for (int t = gtid; t < NC * NPIX; t += NTHR) {
        int o = t / NPIX, n = t % NPIX;
        int y = n / HW, x = n % HW;
        float acc = net_b[o];
        #pragma unroll
        for (int c = 0; c < 3; c++)
            #pragma unroll
            for (int ky = 0; ky < 3; ky++) {
                int yy = y + ky - 1;
                if (yy < 0 || yy >= HW) continue;
                #pragma unroll
                for (int kx = 0; kx < 3; kx++) {
                    int xx = x + kx - 1;
                    if (xx < 0 || xx >= HW) continue;
                    acc += img[c * NPIX + yy * HW + xx] * net_w[((o * 3 + c) * 3 + ky) * 3 + kx];
                }
            }
        g_u[t] = acc;
    }
    gsync();

    // ================= phase 1: normalize G, build phiT, init softmax ======
    for (int t = gtid; t < HW * HW; t += NTHR) {
        int i = t / HW, j = t % HW;
        float gn = g_Gn[t] / g_gsum[i];
        g_Gn[t] = gn;
        g_GnT[j * HW + i] = gn;
    }
    {
        float* spw = (float*)sraw;                 // [5*6][TPB], 30720 B
        for (int task = bid; task < 144; task += GRID) {
            int tile = task >> 2, rch = task & 3;
            int n = tile * TPB + tid;
            int y = n / HW, x = n % HW;
            float fv[5];
            fv[0] = ((float)x - 47.5f) * (1.0f / 160.0f);
            fv[1] = ((float)y - 47.5f) * (1.0f / 160.0f);
            fv[2] = (img[0 * NPIX + n] - 0.5f) * (1.0f / 3.0f);
            fv[3] = (img[1 * NPIX + n] - 0.5f) * (1.0f / 3.0f);
            fv[4] = (img[2 * NPIX + n] - 0.5f) * (1.0f / 3.0f);
            float a = expf(-0.5f * (fv[0]*fv[0] + fv[1]*fv[1] + fv[2]*fv[2] +
                                    fv[3]*fv[3] + fv[4]*fv[4]));
            #pragma unroll
            for (int v = 0; v < 5; v++) {
                float p = (v == 0) ? a : 1.0f;     // fold 'a' into var-0 powers
                #pragma unroll
                for (int k = 0; k <= 5; k++) {
                    spw[(v * 6 + k) * TPB + tid] = p;
                    p *= fv[v];
                }
            }
            // each thread only reads its own column: no sync needed
            int rbase = rch * 63;
            for (int jj = 0; jj < 63; jj++) {
                int r = rbase + jj;
                unsigned e = g_monoE[r];
                float val = g_monoC[r];
                val *= spw[((e         & 7))       * TPB + tid];
                val *= spw[(6  + ((e >> 3)  & 7))  * TPB + tid];
                val *= spw[(12 + ((e >> 6)  & 7))  * TPB + tid];
                val *= spw[(18 + ((e >> 9)  & 7))  * TPB + tid];
                val *= spw[(24 + ((e >> 12) & 7))  * TPB + tid];
                g_phiT[(size_t)r * NPIX + n] = val;
            }
        }
    }
    // initial softmax (warp per pixel, lane = class)
    {
        int gw = gtid >> 5;
        for (int n = gw; n < NPIX; n += NTHR / 32) {
            float q = (lane < NC) ? g_u[lane * NPIX + n] : -1e30f;
            float m = q;
            #pragma unroll
            for (int o = 16; o > 0; o >>= 1) m = fmaxf(m, __shfl_xor_sync(0xffffffffu, m, o));
            float e = (lane < NC) ? expf(q - m) : 0.0f;
            float ss = e;
            #pragma unroll
            for (int o = 16; o > 0; o >>= 1) ss += __shfl_xor_sync(0xffffffffu, ss, o);
            if (lane < NC) g_s[lane * NPIX + n] = e / ss;
        }
    }
    gsync();

    // ======================= phase 2: M0[r] = sum_n phiT ====================
    {
        float* red = (float*)sraw;
        for (int r = bid; r < RD; r += GRID) {
            const float* row = g_phiT + (size_t)r * NPIX;
            float acc = 0.0f;
            for (int i = tid; i < NPIX; i += TPB) acc += row[i];
            __syncthreads();                       // protect red[] reuse
            red[tid] = acc;
            __syncthreads();
            for (int s2 = 128; s2 > 0; s2 >>= 1) {
                if (tid < s2) red[tid] += red[tid + s2];
                __syncthreads();
            }
            if (tid == 0) g_M0[r] = red[0];
        }
    }
    gsync();

    // ======================= mean-field iterations ==========================
    for (int it = 0; it < 5; it++) {
        // ---- phase A: [it0: normbl], moments, spatial pass X ----
        if (it == 0) {
            for (int n = gtid; n < NPIX; n += NTHR) {
                float acc = 0.0f;
                for (int r = 0; r < RD; r++)
                    acc += g_phiT[(size_t)r * NPIX + n] * g_M0[r];
                g_normbl[n] = acc;
            }
        }
        {   // moments: g_mom[c][r] += sum_n phiT[r][n]*s[c][n]
            float* sS = (float*)sraw;              // [NC][384], 32256 B
            for (int task = bid; task < 192; task += GRID) {
                int ns = task % 24, rb = task / 24;
                int n0 = ns * 384;
                __syncthreads();
                for (int idx = tid; idx < NC * 384; idx += TPB) {
                    int c = idx / 384, i = idx % 384;
                    sS[c * 384 + i] = g_s[c * NPIX + n0 + i];
                }
                __syncthreads();
                int w = tid >> 5;
                int r0 = rb * 32 + w * 4;
                if (r0 < RD) {
                    float acc[4][NC];
                    #pragma unroll
                    for (int k = 0; k < 4; k++)
                        #pragma unroll
                        for (int c = 0; c < NC; c++) acc[k][c] = 0.0f;
                    for (int i = 0; i < 12; i++) {
                        int nn = i * 32 + lane;
                        float p0 = g_phiT[(size_t)(r0 + 0) * NPIX + n0 + nn];
                        float p1 = g_phiT[(size_t)(r0 + 1) * NPIX + n0 + nn];
                        float p2 = g_phiT[(size_t)(r0 + 2) * NPIX + n0 + nn];
                        float p3 = g_phiT[(size_t)(r0 + 3) * NPIX + n0 + nn];
                        #pragma unroll
                        for (int c = 0; c < NC; c++) {
                            float sv = sS[c * 384 + nn];
                            acc[0][c] += p0 * sv;
                            acc[1][c] += p1 * sv;
                            acc[2][c] += p2 * sv;
                            acc[3][c] += p3 * sv;
                        }
                    }
                    #pragma unroll
                    for (int k = 0; k < 4; k++)
                        #pragma unroll
                        for (int c = 0; c < NC; c++) {
                            float v = acc[k][c];
                            #pragma unroll
                            for (int o = 16; o > 0; o >>= 1)
                                v += __shfl_xor_sync(0xffffffffu, v, o);
                            if (lane == 0) atomicAdd(&g_mom[c * RD + r0 + k], v);
                        }
                }
            }
        }
        // spatial pass X: tmp[c][y][x] = sum_xp GnT[xp][x]*s[c][y][xp]
        for (int o = gtid; o < NC * NPIX; o += NTHR) {
            int c = o / NPIX, rem = o % NPIX;
            int y = rem / HW, x = rem % HW;
            const float* srow = g_s + c * NPIX + y * HW;
            float acc = 0.0f;
            for (int xp = 0; xp < HW; xp++)
                acc += g_GnT[xp * HW + x] * srow[xp];
            g_tmp[o] = acc;
        }
        gsync();

        // ---- phase B: spatial pass Y + bilateral backprojection ----
        for (int o = gtid; o < NC * NPIX; o += NTHR) {
            int c = o / NPIX, rem = o % NPIX;
            int y = rem / HW, x = rem % HW;
            float acc = 0.0f;
            for (int yp = 0; yp < HW; yp++)
                acc += g_Gn[y * HW + yp] * g_tmp[c * NPIX + yp * HW + x];
            g_sp[o] = acc;
        }
        {   // bl partials: part[rsp][c][n] = phiT[rchunk][n].mom[c][rchunk]
            unsigned long long* sM2 = (unsigned long long*)sraw;  // 756*8 B
            if (bid < 126) {
                int n2c = bid % 18, rsp = bid / 18;
                int rb = rsp * RCH;
                for (int idx = tid; idx < NC * RCH; idx += TPB) {
                    int c = idx / RCH, j = idx % RCH;
                    unsigned ui = __float_as_uint(g_mom[c * RD + rb + j]);
                    sM2[idx] = ((unsigned long long)ui << 32) | (unsigned long long)ui;
                }
                __syncthreads();
                int n2 = n2c * TPB + tid;                 // float2 pair index
                unsigned long long acc[NC];
                #pragma unroll
                for (int c = 0; c < NC; c++) acc[c] = 0ull;
                for (int j = 0; j < RCH; j++) {
                    const unsigned long long* rowp =
                        reinterpret_cast<const unsigned long long*>(
                            g_phiT + (size_t)(rb + j) * NPIX);
                    unsigned long long p = rowp[n2];
                    #pragma unroll
                    for (int c = 0; c < NC; c++) {
                        asm("fma.rn.f32x2 %0, %1, %2, %0;"
                            : "+l"(acc[c]) : "l"(p), "l"(sM2[c * RCH + j]));
                    }
                }
                #pragma unroll
                for (int c = 0; c < NC; c++) {
                    float2 v;
                    v.x = __uint_as_float((unsigned)(acc[c] & 0xffffffffull));
                    v.y = __uint_as_float((unsigned)(acc[c] >> 32));
                    reinterpret_cast<float2*>(
                        g_part + (size_t)(rsp * NC + c) * NPIX)[n2] = v;
                }
            }
        }
        gsync();

        // ---- phase C: combine + mixing + softmax; zero mom for next iter ----
        {
            float* sW1 = (float*)sraw;
            float* sW2 = sW1 + NC * NC;
            float* sCv = sW2 + NC * NC;
            for (int i = tid; i < NC * NC; i += TPB) { sW1[i] = g_W1[i]; sW2[i] = g_W2[i]; }
            if (tid < NC) sCv[tid] = g_cvec[tid];
            __syncthreads();
            for (int t = gtid; t < NC * RD; t += NTHR) g_mom[t] = 0.0f;
            int gw = gtid >> 5;
            for (int n = gw; n < NPIX; n += NTHR / 32) {
                float bl = 0.0f, sp = 0.0f, uu = 0.0f;
                if (lane < NC) {
                    float num = 0.0f;
                    #pragma unroll
                    for (int s2 = 0; s2 < RSPLIT; s2++)
                        num += g_part[(size_t)(s2 * NC + lane) * NPIX + n];
                    bl = num / g_normbl[n];
                    sp = g_sp[lane * NPIX + n];
                    uu = g_u[lane * NPIX + n];
                }
                float pair = (lane < NC) ? sCv[lane] : 0.0f;
                #pragma unroll
                for (int cp = 0; cp < NC; cp++) {
                    float spv = __shfl_sync(0xffffffffu, sp, cp);
                    float blv = __shfl_sync(0xffffffffu, bl, cp);
                    if (lane < NC) pair += sW1[lane * NC + cp] * spv + sW2[lane * NC + cp] * blv;
                }
                float q = (lane < NC) ? (uu - pair) : -1e30f;
                float m = q;
                #pragma unroll
                for (int o = 16; o > 0; o >>= 1) m = fmaxf(m, __shfl_xor_sync(0xffffffffu, m, o));
                float e = (lane < NC) ? expf(q - m) : 0.0f;
                float ssum = e;
                #pragma unroll
                for (int o = 16; o > 0; o >>= 1) ssum += __shfl_xor_sync(0xffffffffu, ssum, o);
                float sv = e / ssum;
                if (lane < NC) {
                    g_s[lane * NPIX + n] = sv;
                    if (it == 4) out[lane * NPIX + n] = sv;
                }
            }
        }
        gsync();
    }
}

// ------------------------------ launch -------------------------------------
extern "C" void kernel_launch(void* const* d_in, const int* in_sizes, int n_in,
                              void* d_out, int out_size) {
    const float* image  = (const float*)d_in[0];
    const float* net_w  = (const float*)d_in[1];
    const float* net_b  = (const float*)d_in[2];
    const float* sp_w   = (const float*)d_in[3];
    const float* sp_b   = (const float*)d_in[4];
    const float* bl_w   = (const float*)d_in[5];
    const float* bl_b   = (const float*)d_in[6];
    const float* comp_w = (const float*)d_in[7];
    const float* comp_b = (const float*)d_in[8];
    float* out = (float*)d_out;

    crf_all<<<GRID, TPB>>>(image, net_w, net_b, sp_w, sp_b,
                           bl_w, bl_b, comp_w, comp_b, out);
}

// round 5
// speedup vs baseline: 2.0599x; 2.0599x over previous
#include <cuda_runtime.h>
#include <math.h>

// ---------------------------------------------------------------------------
// CRF-as-RNN forward — persistent kernel v2.
//  - 148 blocks x 512 threads (16 warps/SM, regs<=128: no spills in hot loops)
//  - spatial filter: separable 1D Gaussian, truncated to +-16 taps (5.5 sigma)
//  - bilateral: low-rank feature map, degree-5 Taylor, R=252 monomials
//  - phase/barrier structure balanced across all 148 SMs
// ---------------------------------------------------------------------------

typedef unsigned long long ull;

static constexpr int HW   = 96;
static constexpr int NPIX = HW * HW;        // 9216
static constexpr int NC   = 21;
static constexpr int RD   = 252;
static constexpr int RSPLIT = 14;
static constexpr int RCH  = RD / RSPLIT;    // 18
static constexpr int GRID = 148;
static constexpr int TPB  = 512;
static constexpr int NTHR = GRID * TPB;     // 75776
static constexpr int KR   = 16;             // spatial kernel radius
static constexpr int KW   = 2 * KR + 1;     // 33
static constexpr int NPAIR = NPIX / 2;      // 4608

// ------------------------- device scratch ----------------------------------
__device__ float g_u[NC * NPIX];
__device__ float g_s[NC * NPIX];
__device__ float g_tmp[NC * NPIX];
__device__ float g_sp[NC * NPIX];
__device__ float g_ker[KW];
__device__ float g_gsx[HW];
__device__ float g_phiT[(size_t)RD * NPIX];       // 9.3 MB [r][n]
__device__ float g_M0[RD];
__device__ float g_normbl[NPIX];
__device__ float g_part[(size_t)RSPLIT * NC * NPIX];
__device__ float g_mom[NC * RD];                  // [c][r]
__device__ float g_W1[NC * NC], g_W2[NC * NC], g_cvec[NC];
__device__ unsigned g_barCount = 0;
__device__ volatile unsigned g_barGen = 0;

// grid-wide barrier: sense-reversal counter. Safe: 148 blocks, 1 per SM.
__device__ __forceinline__ void gsync() {
    __syncthreads();
    __threadfence();
    if (threadIdx.x == 0) {
        unsigned my = g_barGen;
        if (atomicAdd(&g_barCount, 1u) == GRID - 1u) {
            g_barCount = 0u;
            __threadfence();
            g_barGen = my + 1u;
        } else {
            while (g_barGen == my) { __nanosleep(64); }
        }
    }
    __syncthreads();
    __threadfence();
}

__device__ __forceinline__ void fma2(ull& acc, ull a, ull b) {
    asm("fma.rn.f32x2 %0, %1, %2, %0;" : "+l"(acc) : "l"(a), "l"(b));
}

__global__ __launch_bounds__(TPB, 1) void crf_all(
    const float* __restrict__ img,
    const float* __restrict__ net_w, const float* __restrict__ net_b,
    const float* __restrict__ sp_w,  const float* __restrict__ sp_b,
    const float* __restrict__ bl_w,  const float* __restrict__ bl_b,
    const float* __restrict__ comp_w,const float* __restrict__ comp_b,
    float* __restrict__ out)
{
    __shared__ __align__(16) char sraw[43008];
    const int tid  = threadIdx.x;
    const int bid  = blockIdx.x;
    const int gtid = bid * TPB + tid;
    const int lane = tid & 31;

    // ======================= phase 0: independent setup =====================
    for (int t = gtid; t < RD; t += NTHR) g_M0[t] = 0.0f;
    for (int t = gtid; t < NC * RD; t += NTHR) g_mom[t] = 0.0f;
    for (int t = gtid; t < KW; t += NTHR) {
        float d = (float)(t - KR) * (1.0f / 3.0f);
        g_ker[t] = expf(-0.5f * d * d);
    }
    for (int t = gtid; t < HW; t += NTHR) {
        float acc = 0.0f;
        for (int d = 0; d < KW; d++) {
            int xx = t + d - KR;
            if (xx >= 0 && xx < HW) {
                float dd = (float)(d - KR) * (1.0f / 3.0f);
                acc += expf(-0.5f * dd * dd);
            }
        }
        g_gsx[t] = acc;
    }
    for (int t = gtid; t < NC * NC; t += NTHR) {
        int o = t / NC, k = t % NC;
        float a1 = 0.0f, a2 = 0.0f;
        for (int c = 0; c < NC; c++) {
            a1 += comp_w[o * NC + c] * sp_w[c * NC + k];
            a2 += comp_w[o * NC + c] * bl_w[c * NC + k];
        }
        g_W1[t] = a1; g_W2[t] = a2;
    }
    for (int t = gtid; t < NC; t += NTHR) {
        float cv = comp_b[t];
        for (int c = 0; c < NC; c++) cv += comp_w[t * NC + c] * (sp_b[c] + bl_b[c]);
        g_cvec[t] = cv;
    }
    // unary 3x3 SAME conv
    for (int t = gtid; t < NC * NPIX; t += NTHR) {
        int o = t / NPIX, n = t % NPIX;
        int y = n / HW, x = n % HW;
        float acc = net_b[o];
        #pragma unroll
        for (int c = 0; c < 3; c++)
            #pragma unroll
            for (int ky = 0; ky < 3; ky++) {
                int yy = y + ky - 1;
                if (yy < 0 || yy >= HW) continue;
                #pragma unroll
                for (int kx = 0; kx < 3; kx++) {
                    int xx = x + kx - 1;
                    if (xx < 0 || xx >= HW) continue;
                    acc += img[c * NPIX + yy * HW + xx] * net_w[((o * 3 + c) * 3 + ky) * 3 + kx];
                }
            }
        g_u[t] = acc;
    }
    gsync();

    // ====== phase 1: build phiT (+M0 via atomics), initial softmax ==========
    {
        // warp-task = (32-px group g<288, r-third tau<3); incremental monomials
        const float ISQ[7] = {0.0f, 1.0f, 0.70710678f, 0.57735027f,
                              0.5f, 0.44721360f, 0.40824829f};
        int wgl = gtid >> 5;
        for (int wt = wgl; wt < 288 * 3; wt += NTHR / 32) {
            int g = wt / 3, tau = wt % 3;
            int rlo = tau * 84, rhi = rlo + 84;
            int n = g * 32 + lane;
            int y = n / HW, x = n % HW;
            float f0 = ((float)x - 47.5f) * (1.0f / 160.0f);
            float f1 = ((float)y - 47.5f) * (1.0f / 160.0f);
            float f2 = (img[0 * NPIX + n] - 0.5f) * (1.0f / 3.0f);
            float f3 = (img[1 * NPIX + n] - 0.5f) * (1.0f / 3.0f);
            float f4 = (img[2 * NPIX + n] - 0.5f) * (1.0f / 3.0f);
            float a = expf(-0.5f * (f0*f0 + f1*f1 + f2*f2 + f3*f3 + f4*f4));
            int r = 0;
            float v0 = a;
            for (int m0 = 0; m0 <= 5; m0++) {
                float v1 = v0;
                for (int m1 = 0; m1 <= 5 - m0; m1++) {
                    float v2 = v1;
                    for (int m2 = 0; m2 <= 5 - m0 - m1; m2++) {
                        float v3 = v2;
                        for (int m3 = 0; m3 <= 5 - m0 - m1 - m2; m3++) {
                            float v4 = v3;
                            for (int m4 = 0; m4 <= 5 - m0 - m1 - m2 - m3; m4++) {
                                if (r >= rlo && r < rhi) {
                                    g_phiT[(size_t)r * NPIX + n] = v4;
                                    float sv = v4;
                                    #pragma unroll
                                    for (int o2 = 16; o2 > 0; o2 >>= 1)
                                        sv += __shfl_xor_sync(0xffffffffu, sv, o2);
                                    if (lane == 0) atomicAdd(&g_M0[r], sv);
                                }
                                r++;
                                v4 *= f4 * ISQ[m4 + 1];
                            }
                            v3 *= f3 * ISQ[m3 + 1];
                        }
                        v2 *= f2 * ISQ[m2 + 1];
                    }
                    v1 *= f1 * ISQ[m1 + 1];
                }
                v0 *= f0 * ISQ[m0 + 1];
            }
        }
    }
    // initial softmax, 64 px per block across 144 blocks
    if (bid < 144 && tid < 64) {
        int n = bid * 64 + tid;
        float q[NC];
        float m = -1e30f;
        #pragma unroll
        for (int c = 0; c < NC; c++) { q[c] = g_u[c * NPIX + n]; m = fmaxf(m, q[c]); }
        float ss = 0.0f;
        #pragma unroll
        for (int c = 0; c < NC; c++) { q[c] = expf(q[c] - m); ss += q[c]; }
        float inv = 1.0f / ss;
        #pragma unroll
        for (int c = 0; c < NC; c++) g_s[c * NPIX + n] = q[c] * inv;
    }
    gsync();

    // ======================= mean-field iterations ==========================
    for (int it = 0; it < 5; it++) {
        // ---- phase A: [it0: normbl], moments, spatial pass X ----
        if (it == 0 && bid < 144 && tid < 64) {
            int n = bid * 64 + tid;
            float acc = 0.0f;
            for (int r = 0; r < RD; r++)
                acc += g_phiT[(size_t)r * NPIX + n] * g_M0[r];
            g_normbl[n] = acc;
        }
        {   // moments: g_mom[c][r] += sum_n phiT[r][n]*s[c][n]
            float* sS = (float*)sraw;                    // [NC][256]
            const ull* sS2 = (const ull*)sraw;
            for (int task = bid; task < 576; task += GRID) {
                int ns = task / 16, rb = task % 16;
                int n0 = ns * 256;
                __syncthreads();
                for (int i2 = tid; i2 < NC * 256; i2 += TPB) {
                    int c = i2 >> 8, i = i2 & 255;
                    sS[c * 256 + i] = g_s[c * NPIX + n0 + i];
                }
                __syncthreads();
                int w = tid >> 5;
                int r = rb * 16 + w;
                if (r < RD) {
                    const ull* prow = (const ull*)(g_phiT + (size_t)r * NPIX);
                    ull acc[NC];
                    #pragma unroll
                    for (int c = 0; c < NC; c++) acc[c] = 0ull;
                    #pragma unroll
                    for (int i = 0; i < 4; i++) {
                        ull p = prow[n0 / 2 + i * 32 + lane];
                        #pragma unroll
                        for (int c = 0; c < NC; c++)
                            fma2(acc[c], p, sS2[c * 128 + i * 32 + lane]);
                    }
                    #pragma unroll
                    for (int c = 0; c < NC; c++) {
                        float v = __uint_as_float((unsigned)(acc[c] & 0xffffffffull))
                                + __uint_as_float((unsigned)(acc[c] >> 32));
                        #pragma unroll
                        for (int o2 = 16; o2 > 0; o2 >>= 1)
                            v += __shfl_xor_sync(0xffffffffu, v, o2);
                        if (lane == 0) atomicAdd(&g_mom[c * RD + r], v);
                    }
                }
            }
        }
        // spatial pass X (truncated 33-tap conv along x)
        for (int o = gtid; o < NC * NPIX; o += NTHR) {
            int rem = o % NPIX;
            int x = rem % HW;
            const float* srow = g_s + (o - x);
            float acc = 0.0f;
            #pragma unroll
            for (int d = 0; d < KW; d++) {
                int xx = x + d - KR;
                if (xx >= 0 && xx < HW) acc += g_ker[d] * srow[xx];
            }
            g_tmp[o] = acc;
        }
        gsync();

        // ---- phase B: spatial pass Y + normalize; bilateral backprojection --
        for (int o = gtid; o < NC * NPIX; o += NTHR) {
            int c = o / NPIX, rem = o % NPIX;
            int y = rem / HW, x = rem % HW;
            float acc = 0.0f;
            #pragma unroll
            for (int d = 0; d < KW; d++) {
                int yy = y + d - KR;
                if (yy >= 0 && yy < HW) acc += g_ker[d] * g_tmp[c * NPIX + yy * HW + x];
            }
            g_sp[o] = acc / (g_gsx[y] * g_gsx[x]);
        }
        {   // bl: part[rsp][c][pair] = phiT[rchunk][pair] . mom[c][rchunk]
            ull* sM2 = (ull*)sraw;                       // 5292 * 8 B
            if (bid * TPB < NPAIR * RSPLIT) {
                for (int i2 = tid; i2 < NC * RD; i2 += TPB) {
                    unsigned ui = __float_as_uint(g_mom[i2]);
                    sM2[i2] = ((ull)ui << 32) | (ull)ui;
                }
            }
            __syncthreads();
            for (int t = gtid; t < NPAIR * RSPLIT; t += NTHR) {
                int rsp = t / NPAIR, n2 = t % NPAIR;
                int rb = rsp * RCH;
                ull acc[NC];
                #pragma unroll
                for (int c = 0; c < NC; c++) acc[c] = 0ull;
                for (int j = 0; j < RCH; j++) {
                    ull p = ((const ull*)g_phiT)[(size_t)(rb + j) * NPAIR + n2];
                    #pragma unroll
                    for (int c = 0; c < NC; c++)
                        fma2(acc[c], p, sM2[c * RD + rb + j]);
                }
                #pragma unroll
                for (int c = 0; c < NC; c++)
                    ((ull*)g_part)[(size_t)(rsp * NC + c) * NPAIR + n2] = acc[c];
            }
        }
        gsync();

        // ---- phase C: combine + mixing + softmax; zero mom for next iter ----
        {
            float* sW1 = (float*)sraw;
            float* sW2 = sW1 + NC * NC;
            float* sCv = sW2 + NC * NC;
            float* sBL = sCv + NC;                       // [64][21]
            float* sSP = sBL + 64 * NC;
            float* sQ  = sSP + 64 * NC;
            for (int i = tid; i < NC * NC; i += TPB) { sW1[i] = g_W1[i]; sW2[i] = g_W2[i]; }
            if (tid < NC) sCv[tid] = g_cvec[tid];
            __syncthreads();
            for (int t = gtid; t < NC * RD; t += NTHR) g_mom[t] = 0.0f;
            if (bid < 144 && tid < 64) {
                int n = bid * 64 + tid;
                float* tb = sBL + tid * NC;
                float* ts = sSP + tid * NC;
                float* tq = sQ  + tid * NC;
                float invnb = 1.0f / g_normbl[n];
                #pragma unroll
                for (int c = 0; c < NC; c++) {
                    float acc = 0.0f;
                    #pragma unroll
                    for (int rsp = 0; rsp < RSPLIT; rsp++)
                        acc += g_part[(size_t)(rsp * NC + c) * NPIX + n];
                    tb[c] = acc * invnb;
                    ts[c] = g_sp[c * NPIX + n];
                }
                for (int o = 0; o < NC; o++) {
                    float pair = sCv[o];
                    #pragma unroll
                    for (int c = 0; c < NC; c++)
                        pair += sW1[o * NC + c] * ts[c] + sW2[o * NC + c] * tb[c];
                    tq[o] = g_u[o * NPIX + n] - pair;
                }
                float m = -1e30f;
                for (int o = 0; o < NC; o++) m = fmaxf(m, tq[o]);
                float ssum = 0.0f;
                for (int o = 0; o < NC; o++) { tq[o] = expf(tq[o] - m); ssum += tq[o]; }
                float inv = 1.0f / ssum;
                for (int o = 0; o < NC; o++) {
                    float sv = tq[o] * inv;
                    g_s[o * NPIX + n] = sv;
                    if (it == 4) out[o * NPIX + n] = sv;
                }
            }
        }
        gsync();
    }
}

// ------------------------------ launch -------------------------------------
extern "C" void kernel_launch(void* const* d_in, const int* in_sizes, int n_in,
                              void* d_out, int out_size) {
    const float* image  = (const float*)d_in[0];
    const float* net_w  = (const float*)d_in[1];
    const float* net_b  = (const float*)d_in[2];
    const float* sp_w   = (const float*)d_in[3];
    const float* sp_b   = (const float*)d_in[4];
    const float* bl_w   = (const float*)d_in[5];
    const float* bl_b   = (const float*)d_in[6];
    const float* comp_w = (const float*)d_in[7];
    const float* comp_b = (const float*)d_in[8];
    float* out = (float*)d_out;

    crf_all<<<GRID, TPB>>>(image, net_w, net_b, sp_w, sp_b,
                           bl_w, bl_b, comp_w, comp_b, out);
}

// round 7
// speedup vs baseline: 2.3348x; 1.1334x over previous
#include <cuda_runtime.h>
#include <math.h>

// ---------------------------------------------------------------------------
// CRF-as-RNN forward — persistent kernel v3.
//  - 148 blocks x 512 threads
//  - CG-style grid barrier: thread-0-only release-atom / acquire-spin
//    (no per-thread gpu-scope membars)
//  - spatial filter: separable 1D Gaussian, truncated to +-16 taps
//  - bilateral: low-rank feature map, degree-5 Taylor, R=252 monomials
// ---------------------------------------------------------------------------

typedef unsigned long long ull;

static constexpr int HW   = 96;
static constexpr int NPIX = HW * HW;        // 9216
static constexpr int NC   = 21;
static constexpr int RD   = 252;
static constexpr int RSPLIT = 14;
static constexpr int RCH  = RD / RSPLIT;    // 18
static constexpr int GRID = 148;
static constexpr int TPB  = 512;
static constexpr int NTHR = GRID * TPB;     // 75776
static constexpr int KR   = 16;
static constexpr int KW   = 2 * KR + 1;     // 33
static constexpr int NPAIR = NPIX / 2;      // 4608
static constexpr int PXB  = 64;             // pixels per block in phase C
static constexpr int PST  = 65;             // padded stride (bank-conflict-free)

// ------------------------- device scratch ----------------------------------
__device__ float g_u[NC * NPIX];
__device__ float g_s[NC * NPIX];
__device__ float g_tmp[NC * NPIX];
__device__ float g_sp[NC * NPIX];
__device__ float g_ker[KW];
__device__ float g_gsx[HW];
__device__ float g_phiT[(size_t)RD * NPIX];       // 9.3 MB [r][n]
__device__ float g_M0[RD];
__device__ float g_normbl[NPIX];
__device__ float g_part[(size_t)RSPLIT * NC * NPIX];
__device__ float g_mom[NC * RD];                  // [c][r]
__device__ float g_W1[NC * NC], g_W2[NC * NC], g_cvec[NC];
__device__ unsigned g_barCount = 0;
__device__ unsigned g_barGen = 0;

// CG-style grid barrier. 148 blocks == 148 SMs, all resident: no deadlock.
// bar.sync (block-scope fence) chains all threads' stores into thread 0's
// gpu-scope release-atom; the waiter's ld.acquire + bar.sync completes the
// synchronizes-with edge for every thread. (cooperative_groups sync_grids
// pattern.)
__device__ __forceinline__ void gsync() {
    __syncthreads();
    if (threadIdx.x == 0) {
        unsigned* cnt = &g_barCount;
        unsigned* gen = &g_barGen;
        unsigned my;
        asm volatile("ld.relaxed.gpu.u32 %0, [%1];" : "=r"(my) : "l"(gen));
        unsigned prev;
        asm volatile("atom.add.release.gpu.u32 %0, [%1], 1;"
                     : "=r"(prev) : "l"(cnt) : "memory");
        if (prev == GRID - 1u) {
            asm volatile("st.relaxed.gpu.u32 [%0], %1;" :: "l"(cnt), "r"(0u));
            asm volatile("st.release.gpu.u32 [%0], %1;"
                         :: "l"(gen), "r"(my + 1u) : "memory");
        } else {
            unsigned cur;
            do {
                __nanosleep(32);
                asm volatile("ld.acquire.gpu.u32 %0, [%1];"
                             : "=r"(cur) : "l"(gen) : "memory");
            } while (cur == my);
        }
    }
    __syncthreads();
}

__device__ __forceinline__ void fma2(ull& acc, ull a, ull b) {
    asm("fma.rn.f32x2 %0, %1, %2, %0;" : "+l"(acc) : "l"(a), "l"(b));
}

__global__ __launch_bounds__(TPB, 1) void crf_all(
    const float* __restrict__ img,
    const float* __restrict__ net_w, const float* __restrict__ net_b,
    const float* __restrict__ sp_w,  const float* __restrict__ sp_b,
    const float* __restrict__ bl_w,  const float* __restrict__ bl_b,
    const float* __restrict__ comp_w,const float* __restrict__ comp_b,
    float* __restrict__ out)
{
    __shared__ __align__(16) char sraw[43008];
    const int tid  = threadIdx.x;
    const int bid  = blockIdx.x;
    const int gtid = bid * TPB + tid;
    const int lane = tid & 31;

    // ======================= phase 0: independent setup =====================
    for (int t = gtid; t < RD; t += NTHR) g_M0[t] = 0.0f;
    for (int t = gtid; t < NC * RD; t += NTHR) g_mom[t] = 0.0f;
    for (int t = gtid; t < KW; t += NTHR) {
        float d = (float)(t - KR) * (1.0f / 3.0f);
        g_ker[t] = expf(-0.5f * d * d);
    }
    for (int t = gtid; t < HW; t += NTHR) {
        float acc = 0.0f;
        for (int d = 0; d < KW; d++) {
            int xx = t + d - KR;
            if (xx >= 0 && xx < HW) {
                float dd = (float)(d - KR) * (1.0f / 3.0f);
                acc += expf(-0.5f * dd * dd);
            }
        }
        g_gsx[t] = acc;
    }
    for (int t = gtid; t < NC * NC; t += NTHR) {
        int o = t / NC, k = t % NC;
        float a1 = 0.0f, a2 = 0.0f;
        for (int c = 0; c < NC; c++) {
            a1 += comp_w[o * NC + c] * sp_w[c * NC + k];
            a2 += comp_w[o * NC + c] * bl_w[c * NC + k];
        }
        g_W1[t] = a1; g_W2[t] = a2;
    }
    for (int t = gtid; t < NC; t += NTHR) {
        float cv = comp_b[t];
        for (int c = 0; c < NC; c++) cv += comp_w[t * NC + c] * (sp_b[c] + bl_b[c]);
        g_cvec[t] = cv;
    }
    // unary 3x3 SAME conv
    for (int t = gtid; t < NC * NPIX; t += NTHR) {
        int o = t / NPIX, n = t % NPIX;
        int y = n / HW, x = n % HW;
        float acc = net_b[o];
        #pragma unroll
        for (int c = 0; c < 3; c++)
            #pragma unroll
            for (int ky = 0; ky < 3; ky++) {
                int yy = y + ky - 1;
                if (yy < 0 || yy >= HW) continue;
                #pragma unroll
                for (int kx = 0; kx < 3; kx++) {
                    int xx = x + kx - 1;
                    if (xx < 0 || xx >= HW) continue;
                    acc += img[c * NPIX + yy * HW + xx] * net_w[((o * 3 + c) * 3 + ky) * 3 + kx];
                }
            }
        g_u[t] = acc;
    }
    gsync();

    // ====== phase 1: build phiT (+M0 via atomics), initial softmax ==========
    {
        const float ISQ[7] = {0.0f, 1.0f, 0.70710678f, 0.57735027f,
                              0.5f, 0.44721360f, 0.40824829f};
        int wgl = gtid >> 5;
        for (int wt = wgl; wt < 288 * 3; wt += NTHR / 32) {
            int g = wt / 3, tau = wt % 3;
            int rlo = tau * 84, rhi = rlo + 84;
            int n = g * 32 + lane;
            int y = n / HW, x = n % HW;
            float f0 = ((float)x - 47.5f) * (1.0f / 160.0f);
            float f1 = ((float)y - 47.5f) * (1.0f / 160.0f);
            float f2 = (img[0 * NPIX + n] - 0.5f) * (1.0f / 3.0f);
            float f3 = (img[1 * NPIX + n] - 0.5f) * (1.0f / 3.0f);
            float f4 = (img[2 * NPIX + n] - 0.5f) * (1.0f / 3.0f);
            float a = expf(-0.5f * (f0*f0 + f1*f1 + f2*f2 + f3*f3 + f4*f4));
            int r = 0;
            float v0 = a;
            for (int m0 = 0; m0 <= 5; m0++) {
                float v1 = v0;
                for (int m1 = 0; m1 <= 5 - m0; m1++) {
                    float v2 = v1;
                    for (int m2 = 0; m2 <= 5 - m0 - m1; m2++) {
                        float v3 = v2;
                        for (int m3 = 0; m3 <= 5 - m0 - m1 - m2; m3++) {
                            float v4 = v3;
                            for (int m4 = 0; m4 <= 5 - m0 - m1 - m2 - m3; m4++) {
                                if (r >= rlo && r < rhi) {
                                    g_phiT[(size_t)r * NPIX + n] = v4;
                                    float sv = v4;
                                    #pragma unroll
                                    for (int o2 = 16; o2 > 0; o2 >>= 1)
                                        sv += __shfl_xor_sync(0xffffffffu, sv, o2);
                                    if (lane == 0) atomicAdd(&g_M0[r], sv);
                                }
                                r++;
                                v4 *= f4 * ISQ[m4 + 1];
                            }
                            v3 *= f3 * ISQ[m3 + 1];
                        }
                        v2 *= f2 * ISQ[m2 + 1];
                    }
                    v1 *= f1 * ISQ[m1 + 1];
                }
                v0 *= f0 * ISQ[m0 + 1];
            }
        }
    }
    // initial softmax
    if (bid < 144 && tid < PXB) {
        int n = bid * PXB + tid;
        float q[NC];
        float m = -1e30f;
        #pragma unroll
        for (int c = 0; c < NC; c++) { q[c] = g_u[c * NPIX + n]; m = fmaxf(m, q[c]); }
        float ss = 0.0f;
        #pragma unroll
        for (int c = 0; c < NC; c++) { q[c] = expf(q[c] - m); ss += q[c]; }
        float inv = 1.0f / ss;
        #pragma unroll
        for (int c = 0; c < NC; c++) g_s[c * NPIX + n] = q[c] * inv;
    }
    gsync();

    // ======================= mean-field iterations ==========================
    for (int it = 0; it < 5; it++) {
        // ---- phase A: [it0: normbl], moments, spatial pass X ----
        if (it == 0 && bid < 144 && tid < PXB) {
            int n = bid * PXB + tid;
            float acc = 0.0f;
            for (int r = 0; r < RD; r++)
                acc += g_phiT[(size_t)r * NPIX + n] * g_M0[r];
            g_normbl[n] = acc;
        }
        {   // moments: g_mom[c][r] += sum_n phiT[r][n]*s[c][n]
            float* sS = (float*)sraw;                    // [NC][256]
            const ull* sS2 = (const ull*)sraw;
            for (int task = bid; task < 576; task += GRID) {
                int ns = task / 16, rb = task % 16;
                int n0 = ns * 256;
                __syncthreads();
                for (int i2 = tid; i2 < NC * 256; i2 += TPB) {
                    int c = i2 >> 8, i = i2 & 255;
                    sS[c * 256 + i] = g_s[c * NPIX + n0 + i];
                }
                __syncthreads();
                int w = tid >> 5;
                int r = rb * 16 + w;
                if (r < RD) {
                    const ull* prow = (const ull*)(g_phiT + (size_t)r * NPIX);
                    ull acc[NC];
                    #pragma unroll
                    for (int c = 0; c < NC; c++) acc[c] = 0ull;
                    #pragma unroll
                    for (int i = 0; i < 4; i++) {
                        ull p = prow[n0 / 2 + i * 32 + lane];
                        #pragma unroll
                        for (int c = 0; c < NC; c++)
                            fma2(acc[c], p, sS2[c * 128 + i * 32 + lane]);
                    }
                    #pragma unroll
                    for (int c = 0; c < NC; c++) {
                        float v = __uint_as_float((unsigned)(acc[c] & 0xffffffffull))
                                + __uint_as_float((unsigned)(acc[c] >> 32));
                        #pragma unroll
                        for (int o2 = 16; o2 > 0; o2 >>= 1)
                            v += __shfl_xor_sync(0xffffffffu, v, o2);
                        if (lane == 0) atomicAdd(&g_mom[c * RD + r], v);
                    }
                }
            }
        }
        // spatial pass X (truncated 33-tap conv along x)
        for (int o = gtid; o < NC * NPIX; o += NTHR) {
            int rem = o % NPIX;
            int x = rem % HW;
            const float* srow = g_s + (o - x);
            float acc = 0.0f;
            #pragma unroll
            for (int d = 0; d < KW; d++) {
                int xx = x + d - KR;
                if (xx >= 0 && xx < HW) acc += g_ker[d] * srow[xx];
            }
            g_tmp[o] = acc;
        }
        gsync();

        // ---- phase B: spatial pass Y + normalize; bilateral backprojection --
        for (int o = gtid; o < NC * NPIX; o += NTHR) {
            int c = o / NPIX, rem = o % NPIX;
            int y = rem / HW, x = rem % HW;
            float acc = 0.0f;
            #pragma unroll
            for (int d = 0; d < KW; d++) {
                int yy = y + d - KR;
                if (yy >= 0 && yy < HW) acc += g_ker[d] * g_tmp[c * NPIX + yy * HW + x];
            }
            g_sp[o] = acc / (g_gsx[y] * g_gsx[x]);
        }
        {   // bl: part[rsp][c][pair] = phiT[rchunk][pair] . mom[c][rchunk]
            ull* sM2 = (ull*)sraw;                       // 5292 * 8 B
            for (int i2 = tid; i2 < NC * RD; i2 += TPB) {
                unsigned ui = __float_as_uint(g_mom[i2]);
                sM2[i2] = ((ull)ui << 32) | (ull)ui;
            }
            __syncthreads();
            for (int t = gtid; t < NPAIR * RSPLIT; t += NTHR) {
                int rsp = t / NPAIR, n2 = t % NPAIR;
                int rb = rsp * RCH;
                ull acc[NC];
                #pragma unroll
                for (int c = 0; c < NC; c++) acc[c] = 0ull;
                for (int j = 0; j < RCH; j++) {
                    ull p = ((const ull*)g_phiT)[(size_t)(rb + j) * NPAIR + n2];
                    #pragma unroll
                    for (int c = 0; c < NC; c++)
                        fma2(acc[c], p, sM2[c * RD + rb + j]);
                }
                #pragma unroll
                for (int c = 0; c < NC; c++)
                    ((ull*)g_part)[(size_t)(rsp * NC + c) * NPAIR + n2] = acc[c];
            }
        }
        gsync();

        // ---- phase C: combine + mixing + softmax; zero mom for next iter ----
        {
            float* sW1 = (float*)sraw;                   // 441
            float* sW2 = sW1 + NC * NC;                  // 441
            float* sCv = sW2 + NC * NC;                  // 21
            float* sBL = sCv + NC;                       // NC x PST
            float* sSP = sBL + NC * PST;                 // NC x PST
            float* sQ  = sSP + NC * PST;                 // NC x PST
            float* sIv = sQ  + NC * PST;                 // PXB
            for (int i = tid; i < NC * NC; i += TPB) { sW1[i] = g_W1[i]; sW2[i] = g_W2[i]; }
            if (tid < NC) sCv[tid] = g_cvec[tid];
            for (int t = gtid; t < NC * RD; t += NTHR) g_mom[t] = 0.0f;

            int n0 = bid * PXB;
            bool act = (bid < 144);
            __syncthreads();
            if (act) {
                // 1. combine partials + load sp (coalesced over px)
                for (int t = tid; t < NC * PXB; t += TPB) {
                    int c = t / PXB, px = t % PXB;
                    int n = n0 + px;
                    float acc = 0.0f;
                    #pragma unroll
                    for (int rsp = 0; rsp < RSPLIT; rsp++)
                        acc += g_part[(size_t)(rsp * NC + c) * NPIX + n];
                    sBL[c * PST + px] = acc / g_normbl[n];
                    sSP[c * PST + px] = g_sp[c * NPIX + n];
                }
            }
            __syncthreads();
            if (act) {
                // 2. mixing: q[o][px] = u - pairwise
                for (int t = tid; t < NC * PXB; t += TPB) {
                    int o = t / PXB, px = t % PXB;
                    float pair = sCv[o];
                    #pragma unroll
                    for (int c = 0; c < NC; c++)
                        pair += sW1[o * NC + c] * sSP[c * PST + px]
                              + sW2[o * NC + c] * sBL[c * PST + px];
                    sQ[o * PST + px] = g_u[o * NPIX + n0 + px] - pair;
                }
            }
            __syncthreads();
            if (act && tid < PXB) {
                // 3. softmax over classes (per pixel)
                int px = tid;
                float m = -1e30f;
                #pragma unroll
                for (int o = 0; o < NC; o++) m = fmaxf(m, sQ[o * PST + px]);
                float ssum = 0.0f;
                #pragma unroll
                for (int o = 0; o < NC; o++) {
                    float e = expf(sQ[o * PST + px] - m);
                    sQ[o * PST + px] = e;
                    ssum += e;
                }
                sIv[px] = 1.0f / ssum;
            }
            __syncthreads();
            if (act) {
                // 4. coalesced stores
                for (int t = tid; t < NC * PXB; t += TPB) {
                    int o = t / PXB, px = t % PXB;
                    float sv = sQ[o * PST + px] * sIv[px];
                    g_s[o * NPIX + n0 + px] = sv;
                    if (it == 4) out[o * NPIX + n0 + px] = sv;
                }
            }
        }
        gsync();
    }
}

// ------------------------------ launch -------------------------------------
extern "C" void kernel_launch(void* const* d_in, const int* in_sizes, int n_in,
                              void* d_out, int out_size) {
    const float* image  = (const float*)d_in[0];
    const float* net_w  = (const float*)d_in[1];
    const float* net_b  = (const float*)d_in[2];
    const float* sp_w   = (const float*)d_in[3];
    const float* sp_b   = (const float*)d_in[4];
    const float* bl_w   = (const float*)d_in[5];
    const float* bl_b   = (const float*)d_in[6];
    const float* comp_w = (const float*)d_in[7];
    const float* comp_b = (const float*)d_in[8];
    float* out = (float*)d_out;

    crf_all<<<GRID, TPB>>>(image, net_w, net_b, sp_w, sp_b,
                           bl_w, bl_b, comp_w, comp_b, out);
}